// round 15
// baseline (speedup 1.0000x reference)
#include <cuda_runtime.h>
#include <cuda_fp16.h>
#include <math.h>
#include <stdint.h>

// ---------------- problem constants ----------------
#define BB 4
#define SS 4096
#define DD 1024
#define MM (BB*SS)            // 16384 rows
#define BSD (BB*SS*DD)
#define CH  64                // scan chunks
#define CL  (SS/CH)           // 64 steps per chunk
#define NCARR (CH*BB*DD)

// concatenated transposed-weight row offsets: [q|k|v|g|o|a]
#define WQ_OFF 0
#define WK_OFF (1024*DD)
#define WV_OFF (2048*DD)
#define WG_OFF (3072*DD)
#define WO_OFF (4096*DD)
#define WA_OFF (5120*DD)
#define WT_ROWS 7168
#define NPROJ 6144            // fused projection output width

// ---------------- device scratch (allocation-free) ----------------
__device__ __half g_xnh[BSD], g_xnl[BSD];
__device__ __half g_yh[BSD],  g_yl[BSD];
__device__ float g_proj[(size_t)MM*NPROJ];
__device__ __half g_wt[(size_t)WT_ROWS*DD];
__device__ float g_Ar[NCARR], g_Ai[NCARR], g_Kr[NCARR], g_Ki[NCARR];
__device__ float g_Hr[NCARR], g_Hi[NCARR];

// ---------------- ptx helpers ----------------
__device__ __forceinline__ uint32_t s2u(const void* p) {
    uint32_t a;
    asm("{ .reg .u64 t; cvta.to.shared.u64 t, %1; cvt.u32.u64 %0, t; }" : "=r"(a) : "l"(p));
    return a;
}
__device__ __forceinline__ void cp16(uint32_t s, const void* g) {
    asm volatile("cp.async.cg.shared.global [%0], [%1], 16;" :: "r"(s), "l"(g));
}
__device__ __forceinline__ void cp_commit() { asm volatile("cp.async.commit_group;" ::: "memory"); }
template<int N> __device__ __forceinline__ void cp_wait() {
    asm volatile("cp.async.wait_group %0;" :: "n"(N) : "memory");
}
__device__ __forceinline__ void ldsm4(uint32_t* r, uint32_t addr) {
    asm volatile("ldmatrix.sync.aligned.m8n8.x4.shared.b16 {%0,%1,%2,%3}, [%4];"
        : "=r"(r[0]), "=r"(r[1]), "=r"(r[2]), "=r"(r[3]) : "r"(addr));
}
__device__ __forceinline__ void mma16816(float* c, const uint32_t* a, uint32_t b0, uint32_t b1) {
    asm volatile(
        "mma.sync.aligned.m16n8k16.row.col.f32.f16.f16.f32 "
        "{%0,%1,%2,%3}, {%4,%5,%6,%7}, {%8,%9}, {%0,%1,%2,%3};"
        : "+f"(c[0]), "+f"(c[1]), "+f"(c[2]), "+f"(c[3])
        : "r"(a[0]), "r"(a[1]), "r"(a[2]), "r"(a[3]), "r"(b0), "r"(b1));
}
// SW128 swizzle of (row, byte-col within 128B row)
__device__ __forceinline__ uint32_t swz(uint32_t row, uint32_t kb) {
    uint32_t bo = row*128 + kb;
    return bo ^ ((bo >> 3) & 0x70);
}

// ---------------- fused weight prep: all 6 weights, one launch ----------------
__global__ __launch_bounds__(256) void wprep(
    const float* __restrict__ wq, const float* __restrict__ wk,
    const float* __restrict__ wv, const float* __restrict__ wg,
    const float* __restrict__ wo, const float* __restrict__ wa,
    __half* __restrict__ T)
{
    __shared__ float t[32][33];
    const int z = blockIdx.z;
    const float* W;
    size_t off;
    int N;
    switch (z) {
        case 0: W = wq; off = WQ_OFF; N = 1024; break;
        case 1: W = wk; off = WK_OFF; N = 1024; break;
        case 2: W = wv; off = WV_OFF; N = 1024; break;
        case 3: W = wg; off = WG_OFF; N = 1024; break;
        case 4: W = wo; off = WO_OFF; N = 1024; break;
        default: W = wa; off = WA_OFF; N = 2048; break;
    }
    const int n0 = blockIdx.x * 32;
    if (n0 >= N) return;
    const int k0 = blockIdx.y * 32;
    for (int i = threadIdx.y; i < 32; i += 8)
        t[i][threadIdx.x] = W[(size_t)(k0 + i) * N + n0 + threadIdx.x];
    __syncthreads();
    for (int i = threadIdx.y; i < 32; i += 8) {
        size_t o = off + (size_t)(n0 + i) * DD + k0 + threadIdx.x;
        T[o] = __float2half(t[threadIdx.x][i]);
    }
}

// ---------------- RMSNorm (fused fp16 hi/lo split output; row offset) ----------------
__global__ __launch_bounds__(256) void rmsnorm_split(
    const float* __restrict__ x, const float* __restrict__ scale,
    __half* __restrict__ oh, __half* __restrict__ ol, int row0)
{
    const int row = row0 + blockIdx.x;
    const float* xr = x + (size_t)row * DD;
    float v[4];
    float s = 0.f;
#pragma unroll
    for (int i = 0; i < 4; i++) {
        v[i] = xr[threadIdx.x + i*256];
        s += v[i]*v[i];
    }
#pragma unroll
    for (int o = 16; o > 0; o >>= 1) s += __shfl_xor_sync(0xffffffffu, s, o);
    __shared__ float red[8];
    if ((threadIdx.x & 31) == 0) red[threadIdx.x >> 5] = s;
    __syncthreads();
    float tot = red[0]+red[1]+red[2]+red[3]+red[4]+red[5]+red[6]+red[7];
    float inv = rsqrtf(tot * (1.f/DD) + 1e-6f);
    size_t base = (size_t)row * DD;
#pragma unroll
    for (int i = 0; i < 4; i++) {
        int idx = threadIdx.x + i*256;
        float val = v[i] * inv * scale[idx];
        __half h = __float2half(val);
        oh[base + idx] = h;
        ol[base + idx] = __float2half(val - __half2float(h));
    }
}

// ---------------- HMMA fp16 split-A GEMM core (512 threads, 16 warps) ----------------
#define NSTG 4
#define NCH  16            // 1024 / 64
#define OFF_AH 0
#define OFF_AL 16384
#define OFF_B  32768
#define STAGE_BYTES 49152
#define GEMM_SMEM (NSTG*STAGE_BYTES)

// 512 threads: gcol = tid&7 (8 cols of 16B), r0 = tid>>3 in [0,64) -> 2 row-iters
__device__ __forceinline__ void load_stage(
    uint32_t st, const __half* Ah, const __half* Al,
    const __half* B, int kc, int tid)
{
    const int gcol = tid & 7, r0 = tid >> 3;
    const int ko = kc*64 + gcol*8;
#pragma unroll
    for (int rr = 0; rr < 128; rr += 64) {
        int r = r0 + rr;
        uint32_t bo = r*128 + gcol*16;
        uint32_t sw = bo ^ ((bo >> 3) & 0x70);
        size_t go = (size_t)r * DD + ko;
        cp16(st + OFF_AH + sw, Ah + go);
        cp16(st + OFF_AL + sw, Al + go);
        cp16(st + OFF_B  + sw, B  + go);
    }
}

// mainloop: 16 warps, warp tile 32(M) x 32(N); acc[2][4][4] = 32 regs
__device__ __forceinline__ void gemm_mainloop(
    uint32_t sb, int tid, const __half* pAh, const __half* pAl, const __half* pB,
    int aRow, int bRow, uint32_t kbl, float acc[2][4][4])
{
#pragma unroll
    for (int c = 0; c < NSTG-1; c++) {
        load_stage(sb + c*STAGE_BYTES, pAh, pAl, pB, c, tid);
        cp_commit();
    }

    for (int c = 0; c < NCH; c++) {
        if (c < NCH - (NSTG-1)) cp_wait<NSTG-2>(); else cp_wait<0>();
        __syncthreads();
        if (c + NSTG-1 < NCH) {
            load_stage(sb + ((c + NSTG-1) % NSTG)*STAGE_BYTES, pAh, pAl, pB, c + NSTG-1, tid);
            cp_commit();
        }
        const uint32_t stg = sb + (c % NSTG)*STAGE_BYTES;
#pragma unroll
        for (int ks = 0; ks < 4; ks++) {
            const uint32_t kb = ks*32 + kbl;
            uint32_t ah[2][4], al[2][4], bf[2][4];
            ldsm4(ah[0], stg + OFF_AH + swz(aRow,      kb));
            ldsm4(ah[1], stg + OFF_AH + swz(aRow + 16, kb));
            ldsm4(al[0], stg + OFF_AL + swz(aRow,      kb));
            ldsm4(al[1], stg + OFF_AL + swz(aRow + 16, kb));
            ldsm4(bf[0], stg + OFF_B  + swz(bRow,      kb));
            ldsm4(bf[1], stg + OFF_B  + swz(bRow + 16, kb));
            // ah pass: 8 independent MMAs
#pragma unroll
            for (int mt = 0; mt < 2; mt++)
#pragma unroll
                for (int nb = 0; nb < 2; nb++) {
                    mma16816(acc[mt][nb*2],   ah[mt], bf[nb][0], bf[nb][2]);
                    mma16816(acc[mt][nb*2+1], ah[mt], bf[nb][1], bf[nb][3]);
                }
            // al pass: 8 independent MMAs
#pragma unroll
            for (int mt = 0; mt < 2; mt++)
#pragma unroll
                for (int nb = 0; nb < 2; nb++) {
                    mma16816(acc[mt][nb*2],   al[mt], bf[nb][0], bf[nb][2]);
                    mma16816(acc[mt][nb*2+1], al[mt], bf[nb][1], bf[nb][3]);
                }
        }
    }
}

// generic GEMM: C[M, ldc] tile at (m0, n0)
__global__ void __launch_bounds__(512, 1) gemm_f16s(
    const __half* __restrict__ Ah, const __half* __restrict__ Al,
    const __half* __restrict__ B,
    float* __restrict__ C, int ldc)
{
    extern __shared__ char smem[];
    const uint32_t sb = s2u(smem);
    const int tid = threadIdx.x, wid = tid >> 5, lane = tid & 31;
    const int wm = wid & 3, wn = wid >> 2;          // warp grid 4(M) x 4(N)
    const int m0 = blockIdx.y << 7, n0 = blockIdx.x << 7;

    float acc[2][4][4];
#pragma unroll
    for (int i = 0; i < 2; i++)
#pragma unroll
        for (int j = 0; j < 4; j++)
#pragma unroll
            for (int t = 0; t < 4; t++) acc[i][j][t] = 0.f;

    const int aRow = wm*32 + (lane & 15);
    const int bRow = wn*32 + (lane & 15);
    const uint32_t kbl = (uint32_t)(lane >> 4) * 16;

    gemm_mainloop(sb, tid,
                  Ah + (size_t)m0 * DD, Al + (size_t)m0 * DD, B + (size_t)n0 * DD,
                  aRow, bRow, kbl, acc);

    const int erow = lane >> 2;
    const int ecol = (lane & 3) * 2;
#pragma unroll
    for (int mt = 0; mt < 2; mt++) {
#pragma unroll
        for (int nt = 0; nt < 4; nt++) {
            int row = m0 + wm*32 + mt*16 + erow;
            int col = n0 + wn*32 + nt*8 + ecol;
            float2* p0 = (float2*)(C + (size_t)row * ldc + col);
            float2* p1 = (float2*)(C + (size_t)(row + 8) * ldc + col);
            *p0 = make_float2(acc[mt][nt][0], acc[mt][nt][1]);
            *p1 = make_float2(acc[mt][nt][2], acc[mt][nt][3]);
        }
    }
}

// proj GEMM: bx<32 -> cols [0,4096) from wt rows [0,4096); bx>=32 -> cols [4096,6144) from wt rows [WA_OFF,...)
__global__ void __launch_bounds__(512, 1) gemm_proj(
    const __half* __restrict__ Ah, const __half* __restrict__ Al,
    const __half* __restrict__ wt, float* __restrict__ C)
{
    extern __shared__ char smem[];
    const uint32_t sb = s2u(smem);
    const int tid = threadIdx.x, wid = tid >> 5, lane = tid & 31;
    const int wm = wid & 3, wn = wid >> 2;
    const int m0 = blockIdx.y << 7;
    int bx = blockIdx.x;
    const __half* B;
    int n0c;
    if (bx < 32) { B = wt + (size_t)(bx << 7) * DD;                       n0c = bx << 7; }
    else         { B = wt + (size_t)WA_OFF + (size_t)((bx-32) << 7) * DD; n0c = 4096 + ((bx-32) << 7); }

    float acc[2][4][4];
#pragma unroll
    for (int i = 0; i < 2; i++)
#pragma unroll
        for (int j = 0; j < 4; j++)
#pragma unroll
            for (int t = 0; t < 4; t++) acc[i][j][t] = 0.f;

    const int aRow = wm*32 + (lane & 15);
    const int bRow = wn*32 + (lane & 15);
    const uint32_t kbl = (uint32_t)(lane >> 4) * 16;

    gemm_mainloop(sb, tid,
                  Ah + (size_t)m0 * DD, Al + (size_t)m0 * DD, B,
                  aRow, bRow, kbl, acc);

    const int erow = lane >> 2;
    const int ecol = (lane & 3) * 2;
#pragma unroll
    for (int mt = 0; mt < 2; mt++) {
#pragma unroll
        for (int nt = 0; nt < 4; nt++) {
            int row = m0 + wm*32 + mt*16 + erow;
            int col = n0c + wn*32 + nt*8 + ecol;
            float2* p0 = (float2*)(C + (size_t)row * NPROJ + col);
            float2* p1 = (float2*)(C + (size_t)(row + 8) * NPROJ + col);
            *p0 = make_float2(acc[mt][nt][0], acc[mt][nt][1]);
            *p1 = make_float2(acc[mt][nt][2], acc[mt][nt][3]);
        }
    }
}

// ---------------- gate helper ----------------
__device__ __forceinline__ void gate_a(float ar, float ai, float& car, float& cai)
{
    float r = sqrtf(ar*ar + ai*ai);
    float sig = 1.f / (1.f + __expf(-r));
    if (r > 1e-30f) {
        float sc = sig / r;
        car = ar * sc;
        cai = ai * sc;
    } else {
        car = 0.5f;
        cai = 0.f;
    }
}

// proj layout: row-major [MM, 6144]: q|k|v|g|ar|ai
#define PQ 0
#define PK 1024
#define PV 2048
#define PG 3072
#define PAR 4096
#define PAI 5120

// ---------------- scan pass 1 (4 lanes/thread, float4 loads) ----------------
__global__ __launch_bounds__(256) void scan_pass1(
    const float* __restrict__ proj,
    float* __restrict__ Ar, float* __restrict__ Ai,
    float* __restrict__ Kr, float* __restrict__ Ki)
{
    const int idx = blockIdx.x * 256 + threadIdx.x;   // [0, 65536)
    const int d4 = (idx & 255) << 2;
    const int bc = idx >> 8;
    const int b  = bc & (BB-1);
    const int c  = bc >> 2;
    float Are[4], Aim[4], Kre[4], Kim[4];
#pragma unroll
    for (int j = 0; j < 4; j++) { Are[j] = 1.f; Aim[j] = 0.f; Kre[j] = 0.f; Kim[j] = 0.f; }
    const size_t rowbase = (size_t)b * SS + (size_t)c * CL;
    for (int t = 0; t < CL; t++) {
        const float* pr = proj + (rowbase + t) * NPROJ;
        float4 var = *(const float4*)(pr + PAR + d4);
        float4 vai = *(const float4*)(pr + PAI + d4);
        float4 vk  = *(const float4*)(pr + PK  + d4);
        float4 vv  = *(const float4*)(pr + PV  + d4);
        float arr[4] = {var.x, var.y, var.z, var.w};
        float aii[4] = {vai.x, vai.y, vai.z, vai.w};
        float kk [4] = {vk.x,  vk.y,  vk.z,  vk.w};
        float vvv[4] = {vv.x,  vv.y,  vv.z,  vv.w};
#pragma unroll
        for (int j = 0; j < 4; j++) {
            float car, cai;
            gate_a(arr[j], aii[j], car, cai);
            float kv = kk[j] * vvv[j];
            float nAr = car*Are[j] - cai*Aim[j];
            float nAi = car*Aim[j] + cai*Are[j];
            float nKr = car*Kre[j] - cai*Kim[j] + kv;
            float nKi = car*Kim[j] + cai*Kre[j];
            Are[j] = nAr; Aim[j] = nAi; Kre[j] = nKr; Kim[j] = nKi;
        }
    }
    const int cb = ((c << 2) + b) * DD + d4;
    *(float4*)(Ar + cb) = make_float4(Are[0], Are[1], Are[2], Are[3]);
    *(float4*)(Ai + cb) = make_float4(Aim[0], Aim[1], Aim[2], Aim[3]);
    *(float4*)(Kr + cb) = make_float4(Kre[0], Kre[1], Kre[2], Kre[3]);
    *(float4*)(Ki + cb) = make_float4(Kim[0], Kim[1], Kim[2], Kim[3]);
}

// ---------------- scan pass 2 ----------------
__global__ __launch_bounds__(256) void scan_pass2(
    const float* __restrict__ Ar, const float* __restrict__ Ai,
    const float* __restrict__ Kr, const float* __restrict__ Ki,
    float* __restrict__ Hr, float* __restrict__ Hi)
{
    const int idx = blockIdx.x * 256 + threadIdx.x;  // B*D
    const int d = idx & (DD-1);
    const int b = idx >> 10;
    float hr = 0.f, hi = 0.f;
    for (int c = 0; c < CH; c++) {
        const int cidx = ((c << 2) + b) * DD + d;
        Hr[cidx] = hr; Hi[cidx] = hi;
        float ar = Ar[cidx], ai = Ai[cidx];
        float kr = Kr[cidx], ki = Ki[cidx];
        float nhr = ar*hr - ai*hi + kr;
        float nhi = ar*hi + ai*hr + ki;
        hr = nhr; hi = nhi;
    }
}

// ---------------- scan pass 3 (4 lanes/thread; emits y hi/lo fp16) ----------------
__global__ __launch_bounds__(256) void scan_pass3(
    const float* __restrict__ proj,
    const float* __restrict__ Hr, const float* __restrict__ Hi,
    __half* __restrict__ yh, __half* __restrict__ yl)
{
    const int idx = blockIdx.x * 256 + threadIdx.x;
    const int d4 = (idx & 255) << 2;
    const int bc = idx >> 8;
    const int b  = bc & (BB-1);
    const int c  = bc >> 2;
    const int cb = ((c << 2) + b) * DD + d4;
    float4 h0 = *(const float4*)(Hr + cb);
    float4 h1 = *(const float4*)(Hi + cb);
    float hr[4] = {h0.x, h0.y, h0.z, h0.w};
    float hi[4] = {h1.x, h1.y, h1.z, h1.w};
    const size_t rowbase = (size_t)b * SS + (size_t)c * CL;
    for (int t = 0; t < CL; t++) {
        const size_t row = rowbase + t;
        const float* pr = proj + row * NPROJ;
        float4 var = *(const float4*)(pr + PAR + d4);
        float4 vai = *(const float4*)(pr + PAI + d4);
        float4 vk  = *(const float4*)(pr + PK  + d4);
        float4 vv  = *(const float4*)(pr + PV  + d4);
        float4 vq  = *(const float4*)(pr + PQ  + d4);
        float4 vg  = *(const float4*)(pr + PG  + d4);
        float arr[4] = {var.x, var.y, var.z, var.w};
        float aii[4] = {vai.x, vai.y, vai.z, vai.w};
        float kk [4] = {vk.x,  vk.y,  vk.z,  vk.w};
        float vvv[4] = {vv.x,  vv.y,  vv.z,  vv.w};
        float qq [4] = {vq.x,  vq.y,  vq.z,  vq.w};
        float gg [4] = {vg.x,  vg.y,  vg.z,  vg.w};
        __half oh[4], ol[4];
#pragma unroll
        for (int j = 0; j < 4; j++) {
            float car, cai;
            gate_a(arr[j], aii[j], car, cai);
            float kv = kk[j] * vvv[j];
            float nhr = car*hr[j] - cai*hi[j] + kv;
            float nhi = car*hi[j] + cai*hr[j];
            hr[j] = nhr; hi[j] = nhi;
            float silu = gg[j] / (1.f + __expf(-gg[j]));
            float outv = qq[j] * hr[j] * silu;
            oh[j] = __float2half(outv);
            ol[j] = __float2half(outv - __half2float(oh[j]));
        }
        const size_t off = row * DD + d4;
        *(__half2*)(yh + off)     = __halves2half2(oh[0], oh[1]);
        *(__half2*)(yh + off + 2) = __halves2half2(oh[2], oh[3]);
        *(__half2*)(yl + off)     = __halves2half2(ol[0], ol[1]);
        *(__half2*)(yl + off + 2) = __halves2half2(ol[2], ol[3]);
    }
}

// ---------------- launch ----------------
extern "C" void kernel_launch(void* const* d_in, const int* in_sizes, int n_in,
                              void* d_out, int out_size)
{
    const float* x    = (const float*)d_in[0];
    const float* wq   = (const float*)d_in[1];
    const float* wk   = (const float*)d_in[2];
    const float* wv   = (const float*)d_in[3];
    const float* wa   = (const float*)d_in[4];
    const float* wg   = (const float*)d_in[5];
    const float* wo   = (const float*)d_in[6];
    const float* rmsw = (const float*)d_in[7];
    float* out = (float*)d_out;

    __half *xnh, *xnl, *yh, *yl, *wt;
    float *proj;
    float *Ar, *Ai, *Kr, *Ki, *Hr, *Hi;
    cudaGetSymbolAddress((void**)&xnh, g_xnh);
    cudaGetSymbolAddress((void**)&xnl, g_xnl);
    cudaGetSymbolAddress((void**)&yh,  g_yh);
    cudaGetSymbolAddress((void**)&yl,  g_yl);
    cudaGetSymbolAddress((void**)&wt,  g_wt);
    cudaGetSymbolAddress((void**)&proj, g_proj);
    cudaGetSymbolAddress((void**)&Ar, g_Ar);
    cudaGetSymbolAddress((void**)&Ai, g_Ai);
    cudaGetSymbolAddress((void**)&Kr, g_Kr);
    cudaGetSymbolAddress((void**)&Ki, g_Ki);
    cudaGetSymbolAddress((void**)&Hr, g_Hr);
    cudaGetSymbolAddress((void**)&Hi, g_Hi);

    cudaFuncSetAttribute(gemm_f16s, cudaFuncAttributeMaxDynamicSharedMemorySize, GEMM_SMEM);
    cudaFuncSetAttribute(gemm_proj, cudaFuncAttributeMaxDynamicSharedMemorySize, GEMM_SMEM);

    // 1: fused weight prep (all 6 weights)
    wprep<<<dim3(64, 32, 6), dim3(32, 8)>>>(wq, wk, wv, wg, wo, wa, wt);

    // 2-3: RMSNorm in two halves (keeps GEMM at launch #4 for ncu capture)
    rmsnorm_split<<<MM/2, 256>>>(x, rmsw, xnh, xnl, 0);
    rmsnorm_split<<<MM/2, 256>>>(x, rmsw, xnh, xnl, MM/2);

    // 4: fused q|k|v|g|a projection GEMM  [16384 x 6144]
    gemm_proj<<<dim3(48, MM/128), 512, GEMM_SMEM>>>(xnh, xnl, wt, proj);

    // 5-7: chunked associative scan (4-wide vectorized)
    scan_pass1<<<(BB*DD*CH)/(256*4), 256>>>(proj, Ar, Ai, Kr, Ki);
    scan_pass2<<<(BB*DD)/256, 256>>>(Ar, Ai, Kr, Ki, Hr, Hi);
    scan_pass3<<<(BB*DD*CH)/(256*4), 256>>>(proj, Hr, Hi, yh, yl);

    // 8: output projection
    gemm_f16s<<<dim3(8, MM/128), 512, GEMM_SMEM>>>(
        yh, yl, wt + WO_OFF, out, 1024);
}

// round 16
// speedup vs baseline: 1.5922x; 1.5922x over previous
#include <cuda_runtime.h>
#include <cuda_fp16.h>
#include <math.h>
#include <stdint.h>

// ---------------- problem constants ----------------
#define BB 4
#define SS 4096
#define DD 1024
#define MM (BB*SS)            // 16384 rows
#define BSD (BB*SS*DD)
#define CH  64                // scan chunks
#define CL  (SS/CH)           // 64 steps per chunk
#define NCARR (CH*BB*DD)

// concatenated transposed-weight row offsets: [q|k|v|g|o|a]
#define WQ_OFF 0
#define WK_OFF (1024*DD)
#define WV_OFF (2048*DD)
#define WG_OFF (3072*DD)
#define WO_OFF (4096*DD)
#define WA_OFF (5120*DD)
#define WT_ROWS 7168
#define NPROJ 6144            // fused projection output width

// ---------------- device scratch (allocation-free) ----------------
__device__ __half g_xn[BSD];
__device__ __half g_y [BSD];
__device__ float g_proj[(size_t)MM*NPROJ];
__device__ __half g_wt[(size_t)WT_ROWS*DD];
__device__ float g_Ar[NCARR], g_Ai[NCARR], g_Kr[NCARR], g_Ki[NCARR];
__device__ float g_Hr[NCARR], g_Hi[NCARR];

// ---------------- ptx helpers ----------------
__device__ __forceinline__ uint32_t s2u(const void* p) {
    uint32_t a;
    asm("{ .reg .u64 t; cvta.to.shared.u64 t, %1; cvt.u32.u64 %0, t; }" : "=r"(a) : "l"(p));
    return a;
}
__device__ __forceinline__ void cp16(uint32_t s, const void* g) {
    asm volatile("cp.async.cg.shared.global [%0], [%1], 16;" :: "r"(s), "l"(g));
}
__device__ __forceinline__ void cp_commit() { asm volatile("cp.async.commit_group;" ::: "memory"); }
template<int N> __device__ __forceinline__ void cp_wait() {
    asm volatile("cp.async.wait_group %0;" :: "n"(N) : "memory");
}
__device__ __forceinline__ void ldsm4(uint32_t* r, uint32_t addr) {
    asm volatile("ldmatrix.sync.aligned.m8n8.x4.shared.b16 {%0,%1,%2,%3}, [%4];"
        : "=r"(r[0]), "=r"(r[1]), "=r"(r[2]), "=r"(r[3]) : "r"(addr));
}
__device__ __forceinline__ void mma16816(float* c, const uint32_t* a, uint32_t b0, uint32_t b1) {
    asm volatile(
        "mma.sync.aligned.m16n8k16.row.col.f32.f16.f16.f32 "
        "{%0,%1,%2,%3}, {%4,%5,%6,%7}, {%8,%9}, {%0,%1,%2,%3};"
        : "+f"(c[0]), "+f"(c[1]), "+f"(c[2]), "+f"(c[3])
        : "r"(a[0]), "r"(a[1]), "r"(a[2]), "r"(a[3]), "r"(b0), "r"(b1));
}
// SW128 swizzle of (row, byte-col within 128B row)
__device__ __forceinline__ uint32_t swz(uint32_t row, uint32_t kb) {
    uint32_t bo = row*128 + kb;
    return bo ^ ((bo >> 3) & 0x70);
}

// ---------------- fused weight prep: all 6 weights, one launch ----------------
__global__ __launch_bounds__(256) void wprep(
    const float* __restrict__ wq, const float* __restrict__ wk,
    const float* __restrict__ wv, const float* __restrict__ wg,
    const float* __restrict__ wo, const float* __restrict__ wa,
    __half* __restrict__ T)
{
    __shared__ float t[32][33];
    const int z = blockIdx.z;
    const float* W;
    size_t off;
    int N;
    switch (z) {
        case 0: W = wq; off = WQ_OFF; N = 1024; break;
        case 1: W = wk; off = WK_OFF; N = 1024; break;
        case 2: W = wv; off = WV_OFF; N = 1024; break;
        case 3: W = wg; off = WG_OFF; N = 1024; break;
        case 4: W = wo; off = WO_OFF; N = 1024; break;
        default: W = wa; off = WA_OFF; N = 2048; break;
    }
    const int n0 = blockIdx.x * 32;
    if (n0 >= N) return;
    const int k0 = blockIdx.y * 32;
    for (int i = threadIdx.y; i < 32; i += 8)
        t[i][threadIdx.x] = W[(size_t)(k0 + i) * N + n0 + threadIdx.x];
    __syncthreads();
    for (int i = threadIdx.y; i < 32; i += 8) {
        size_t o = off + (size_t)(n0 + i) * DD + k0 + threadIdx.x;
        T[o] = __float2half(t[threadIdx.x][i]);
    }
}

// ---------------- RMSNorm (fp16 output; row offset) ----------------
__global__ __launch_bounds__(256) void rmsnorm_h(
    const float* __restrict__ x, const float* __restrict__ scale,
    __half* __restrict__ o, int row0)
{
    const int row = row0 + blockIdx.x;
    const float* xr = x + (size_t)row * DD;
    float v[4];
    float s = 0.f;
#pragma unroll
    for (int i = 0; i < 4; i++) {
        v[i] = xr[threadIdx.x + i*256];
        s += v[i]*v[i];
    }
#pragma unroll
    for (int off = 16; off > 0; off >>= 1) s += __shfl_xor_sync(0xffffffffu, s, off);
    __shared__ float red[8];
    if ((threadIdx.x & 31) == 0) red[threadIdx.x >> 5] = s;
    __syncthreads();
    float tot = red[0]+red[1]+red[2]+red[3]+red[4]+red[5]+red[6]+red[7];
    float inv = rsqrtf(tot * (1.f/DD) + 1e-6f);
    size_t base = (size_t)row * DD;
#pragma unroll
    for (int i = 0; i < 4; i++) {
        int idx = threadIdx.x + i*256;
        o[base + idx] = __float2half(v[i] * inv * scale[idx]);
    }
}

// ---------------- HMMA fp16 GEMM core (single term) ----------------
#define NSTG 4
#define NCH  16            // 1024 / 64
#define OFF_A 0
#define OFF_B 16384
#define STAGE_BYTES 32768
#define GEMM_SMEM (NSTG*STAGE_BYTES)   // 128KB

__device__ __forceinline__ void load_stage(
    uint32_t st, const __half* A, const __half* B, int kc, int tid)
{
    const int gcol = tid & 7, r0 = tid >> 3;        // 256 threads: r0 in [0,32)
    const int ko = kc*64 + gcol*8;
#pragma unroll
    for (int rr = 0; rr < 128; rr += 32) {
        int r = r0 + rr;
        uint32_t bo = r*128 + gcol*16;
        uint32_t sw = bo ^ ((bo >> 3) & 0x70);
        size_t go = (size_t)r * DD + ko;
        cp16(st + OFF_A + sw, A + go);
        cp16(st + OFF_B + sw, B + go);
    }
}

// mainloop: 8 warps, warp tile 32(M) x 64(N); acc[2][8][4] = 64 regs
__device__ __forceinline__ void gemm_mainloop(
    uint32_t sb, int tid, const __half* pA, const __half* pB,
    int aRow, int bRow, uint32_t kbl, float acc[2][8][4])
{
#pragma unroll
    for (int c = 0; c < NSTG-1; c++) {
        load_stage(sb + c*STAGE_BYTES, pA, pB, c, tid);
        cp_commit();
    }

    for (int c = 0; c < NCH; c++) {
        if (c < NCH - (NSTG-1)) cp_wait<NSTG-2>(); else cp_wait<0>();
        __syncthreads();
        if (c + NSTG-1 < NCH) {
            load_stage(sb + ((c + NSTG-1) % NSTG)*STAGE_BYTES, pA, pB, c + NSTG-1, tid);
            cp_commit();
        }
        const uint32_t stg = sb + (c % NSTG)*STAGE_BYTES;
#pragma unroll
        for (int ks = 0; ks < 4; ks++) {
            const uint32_t kb = ks*32 + kbl;
            uint32_t af[2][4], bf[4][4];
            ldsm4(af[0], stg + OFF_A + swz(aRow,      kb));
            ldsm4(af[1], stg + OFF_A + swz(aRow + 16, kb));
#pragma unroll
            for (int nn = 0; nn < 4; nn++)
                ldsm4(bf[nn], stg + OFF_B + swz(bRow + nn*16, kb));
            // 16 MMAs, each accumulator written once -> RAW distance 16
#pragma unroll
            for (int mt = 0; mt < 2; mt++)
#pragma unroll
                for (int nn = 0; nn < 4; nn++) {
                    mma16816(acc[mt][nn*2],   af[mt], bf[nn][0], bf[nn][2]);
                    mma16816(acc[mt][nn*2+1], af[mt], bf[nn][1], bf[nn][3]);
                }
        }
    }
}

// generic GEMM: C[M, ldc] tile at (m0, n0)
__global__ void __launch_bounds__(256, 1) gemm_f16(
    const __half* __restrict__ A, const __half* __restrict__ B,
    float* __restrict__ C, int ldc)
{
    extern __shared__ char smem[];
    const uint32_t sb = s2u(smem);
    const int tid = threadIdx.x, wid = tid >> 5, lane = tid & 31;
    const int wm = wid & 3, wn = wid >> 2;          // warp grid 4(M) x 2(N)
    const int m0 = blockIdx.y << 7, n0 = blockIdx.x << 7;

    float acc[2][8][4];
#pragma unroll
    for (int i = 0; i < 2; i++)
#pragma unroll
        for (int j = 0; j < 8; j++)
#pragma unroll
            for (int t = 0; t < 4; t++) acc[i][j][t] = 0.f;

    const int aRow = wm*32 + (lane & 15);
    const int bRow = wn*64 + (lane & 15);
    const uint32_t kbl = (uint32_t)(lane >> 4) * 16;

    gemm_mainloop(sb, tid, A + (size_t)m0 * DD, B + (size_t)n0 * DD,
                  aRow, bRow, kbl, acc);

    const int erow = lane >> 2;
    const int ecol = (lane & 3) * 2;
#pragma unroll
    for (int mt = 0; mt < 2; mt++) {
#pragma unroll
        for (int nt = 0; nt < 8; nt++) {
            int row = m0 + wm*32 + mt*16 + erow;
            int col = n0 + wn*64 + nt*8 + ecol;
            float2* p0 = (float2*)(C + (size_t)row * ldc + col);
            float2* p1 = (float2*)(C + (size_t)(row + 8) * ldc + col);
            *p0 = make_float2(acc[mt][nt][0], acc[mt][nt][1]);
            *p1 = make_float2(acc[mt][nt][2], acc[mt][nt][3]);
        }
    }
}

// proj GEMM: bx<32 -> cols [0,4096) from wt rows [0,4096); bx>=32 -> cols [4096,6144) from wt rows [WA_OFF,...)
__global__ void __launch_bounds__(256, 1) gemm_proj(
    const __half* __restrict__ A, const __half* __restrict__ wt,
    float* __restrict__ C)
{
    extern __shared__ char smem[];
    const uint32_t sb = s2u(smem);
    const int tid = threadIdx.x, wid = tid >> 5, lane = tid & 31;
    const int wm = wid & 3, wn = wid >> 2;
    const int m0 = blockIdx.y << 7;
    int bx = blockIdx.x;
    const __half* B;
    int n0c;
    if (bx < 32) { B = wt + (size_t)(bx << 7) * DD;                       n0c = bx << 7; }
    else         { B = wt + (size_t)WA_OFF + (size_t)((bx-32) << 7) * DD; n0c = 4096 + ((bx-32) << 7); }

    float acc[2][8][4];
#pragma unroll
    for (int i = 0; i < 2; i++)
#pragma unroll
        for (int j = 0; j < 8; j++)
#pragma unroll
            for (int t = 0; t < 4; t++) acc[i][j][t] = 0.f;

    const int aRow = wm*32 + (lane & 15);
    const int bRow = wn*64 + (lane & 15);
    const uint32_t kbl = (uint32_t)(lane >> 4) * 16;

    gemm_mainloop(sb, tid, A + (size_t)m0 * DD, B, aRow, bRow, kbl, acc);

    const int erow = lane >> 2;
    const int ecol = (lane & 3) * 2;
#pragma unroll
    for (int mt = 0; mt < 2; mt++) {
#pragma unroll
        for (int nt = 0; nt < 8; nt++) {
            int row = m0 + wm*32 + mt*16 + erow;
            int col = n0c + wn*64 + nt*8 + ecol;
            float2* p0 = (float2*)(C + (size_t)row * NPROJ + col);
            float2* p1 = (float2*)(C + (size_t)(row + 8) * NPROJ + col);
            *p0 = make_float2(acc[mt][nt][0], acc[mt][nt][1]);
            *p1 = make_float2(acc[mt][nt][2], acc[mt][nt][3]);
        }
    }
}

// ---------------- gate helper ----------------
__device__ __forceinline__ void gate_a(float ar, float ai, float& car, float& cai)
{
    float r = sqrtf(ar*ar + ai*ai);
    float sig = 1.f / (1.f + __expf(-r));
    if (r > 1e-30f) {
        float sc = sig / r;
        car = ar * sc;
        cai = ai * sc;
    } else {
        car = 0.5f;
        cai = 0.f;
    }
}

// proj layout: row-major [MM, 6144]: q|k|v|g|ar|ai
#define PQ 0
#define PK 1024
#define PV 2048
#define PG 3072
#define PAR 4096
#define PAI 5120

// ---------------- scan pass 1 (4 lanes/thread, float4 loads) ----------------
__global__ __launch_bounds__(256) void scan_pass1(
    const float* __restrict__ proj,
    float* __restrict__ Ar, float* __restrict__ Ai,
    float* __restrict__ Kr, float* __restrict__ Ki)
{
    const int idx = blockIdx.x * 256 + threadIdx.x;   // [0, 65536)
    const int d4 = (idx & 255) << 2;
    const int bc = idx >> 8;
    const int b  = bc & (BB-1);
    const int c  = bc >> 2;
    float Are[4], Aim[4], Kre[4], Kim[4];
#pragma unroll
    for (int j = 0; j < 4; j++) { Are[j] = 1.f; Aim[j] = 0.f; Kre[j] = 0.f; Kim[j] = 0.f; }
    const size_t rowbase = (size_t)b * SS + (size_t)c * CL;
    for (int t = 0; t < CL; t++) {
        const float* pr = proj + (rowbase + t) * NPROJ;
        float4 var = *(const float4*)(pr + PAR + d4);
        float4 vai = *(const float4*)(pr + PAI + d4);
        float4 vk  = *(const float4*)(pr + PK  + d4);
        float4 vv  = *(const float4*)(pr + PV  + d4);
        float arr[4] = {var.x, var.y, var.z, var.w};
        float aii[4] = {vai.x, vai.y, vai.z, vai.w};
        float kk [4] = {vk.x,  vk.y,  vk.z,  vk.w};
        float vvv[4] = {vv.x,  vv.y,  vv.z,  vv.w};
#pragma unroll
        for (int j = 0; j < 4; j++) {
            float car, cai;
            gate_a(arr[j], aii[j], car, cai);
            float kv = kk[j] * vvv[j];
            float nAr = car*Are[j] - cai*Aim[j];
            float nAi = car*Aim[j] + cai*Are[j];
            float nKr = car*Kre[j] - cai*Kim[j] + kv;
            float nKi = car*Kim[j] + cai*Kre[j];
            Are[j] = nAr; Aim[j] = nAi; Kre[j] = nKr; Kim[j] = nKi;
        }
    }
    const int cb = ((c << 2) + b) * DD + d4;
    *(float4*)(Ar + cb) = make_float4(Are[0], Are[1], Are[2], Are[3]);
    *(float4*)(Ai + cb) = make_float4(Aim[0], Aim[1], Aim[2], Aim[3]);
    *(float4*)(Kr + cb) = make_float4(Kre[0], Kre[1], Kre[2], Kre[3]);
    *(float4*)(Ki + cb) = make_float4(Kim[0], Kim[1], Kim[2], Kim[3]);
}

// ---------------- scan pass 2 ----------------
__global__ __launch_bounds__(256) void scan_pass2(
    const float* __restrict__ Ar, const float* __restrict__ Ai,
    const float* __restrict__ Kr, const float* __restrict__ Ki,
    float* __restrict__ Hr, float* __restrict__ Hi)
{
    const int idx = blockIdx.x * 256 + threadIdx.x;  // B*D
    const int d = idx & (DD-1);
    const int b = idx >> 10;
    float hr = 0.f, hi = 0.f;
    for (int c = 0; c < CH; c++) {
        const int cidx = ((c << 2) + b) * DD + d;
        Hr[cidx] = hr; Hi[cidx] = hi;
        float ar = Ar[cidx], ai = Ai[cidx];
        float kr = Kr[cidx], ki = Ki[cidx];
        float nhr = ar*hr - ai*hi + kr;
        float nhi = ar*hi + ai*hr + ki;
        hr = nhr; hi = nhi;
    }
}

// ---------------- scan pass 3 (4 lanes/thread; emits y fp16) ----------------
__global__ __launch_bounds__(256) void scan_pass3(
    const float* __restrict__ proj,
    const float* __restrict__ Hr, const float* __restrict__ Hi,
    __half* __restrict__ y)
{
    const int idx = blockIdx.x * 256 + threadIdx.x;
    const int d4 = (idx & 255) << 2;
    const int bc = idx >> 8;
    const int b  = bc & (BB-1);
    const int c  = bc >> 2;
    const int cb = ((c << 2) + b) * DD + d4;
    float4 h0 = *(const float4*)(Hr + cb);
    float4 h1 = *(const float4*)(Hi + cb);
    float hr[4] = {h0.x, h0.y, h0.z, h0.w};
    float hi[4] = {h1.x, h1.y, h1.z, h1.w};
    const size_t rowbase = (size_t)b * SS + (size_t)c * CL;
    for (int t = 0; t < CL; t++) {
        const size_t row = rowbase + t;
        const float* pr = proj + row * NPROJ;
        float4 var = *(const float4*)(pr + PAR + d4);
        float4 vai = *(const float4*)(pr + PAI + d4);
        float4 vk  = *(const float4*)(pr + PK  + d4);
        float4 vv  = *(const float4*)(pr + PV  + d4);
        float4 vq  = *(const float4*)(pr + PQ  + d4);
        float4 vg  = *(const float4*)(pr + PG  + d4);
        float arr[4] = {var.x, var.y, var.z, var.w};
        float aii[4] = {vai.x, vai.y, vai.z, vai.w};
        float kk [4] = {vk.x,  vk.y,  vk.z,  vk.w};
        float vvv[4] = {vv.x,  vv.y,  vv.z,  vv.w};
        float qq [4] = {vq.x,  vq.y,  vq.z,  vq.w};
        float gg [4] = {vg.x,  vg.y,  vg.z,  vg.w};
        __half oh[4];
#pragma unroll
        for (int j = 0; j < 4; j++) {
            float car, cai;
            gate_a(arr[j], aii[j], car, cai);
            float kv = kk[j] * vvv[j];
            float nhr = car*hr[j] - cai*hi[j] + kv;
            float nhi = car*hi[j] + cai*hr[j];
            hr[j] = nhr; hi[j] = nhi;
            float silu = gg[j] / (1.f + __expf(-gg[j]));
            oh[j] = __float2half(qq[j] * hr[j] * silu);
        }
        const size_t off = row * DD + d4;
        *(__half2*)(y + off)     = __halves2half2(oh[0], oh[1]);
        *(__half2*)(y + off + 2) = __halves2half2(oh[2], oh[3]);
    }
}

// ---------------- launch ----------------
extern "C" void kernel_launch(void* const* d_in, const int* in_sizes, int n_in,
                              void* d_out, int out_size)
{
    const float* x    = (const float*)d_in[0];
    const float* wq   = (const float*)d_in[1];
    const float* wk   = (const float*)d_in[2];
    const float* wv   = (const float*)d_in[3];
    const float* wa   = (const float*)d_in[4];
    const float* wg   = (const float*)d_in[5];
    const float* wo   = (const float*)d_in[6];
    const float* rmsw = (const float*)d_in[7];
    float* out = (float*)d_out;

    __half *xn, *y, *wt;
    float *proj;
    float *Ar, *Ai, *Kr, *Ki, *Hr, *Hi;
    cudaGetSymbolAddress((void**)&xn, g_xn);
    cudaGetSymbolAddress((void**)&y,  g_y);
    cudaGetSymbolAddress((void**)&wt, g_wt);
    cudaGetSymbolAddress((void**)&proj, g_proj);
    cudaGetSymbolAddress((void**)&Ar, g_Ar);
    cudaGetSymbolAddress((void**)&Ai, g_Ai);
    cudaGetSymbolAddress((void**)&Kr, g_Kr);
    cudaGetSymbolAddress((void**)&Ki, g_Ki);
    cudaGetSymbolAddress((void**)&Hr, g_Hr);
    cudaGetSymbolAddress((void**)&Hi, g_Hi);

    cudaFuncSetAttribute(gemm_f16, cudaFuncAttributeMaxDynamicSharedMemorySize, GEMM_SMEM);
    cudaFuncSetAttribute(gemm_proj, cudaFuncAttributeMaxDynamicSharedMemorySize, GEMM_SMEM);

    // 1: fused weight prep (all 6 weights)
    wprep<<<dim3(64, 32, 6), dim3(32, 8)>>>(wq, wk, wv, wg, wo, wa, wt);

    // 2-3: RMSNorm in two halves (keeps GEMM at launch #4 for ncu capture)
    rmsnorm_h<<<MM/2, 256>>>(x, rmsw, xn, 0);
    rmsnorm_h<<<MM/2, 256>>>(x, rmsw, xn, MM/2);

    // 4: fused q|k|v|g|a projection GEMM  [16384 x 6144]
    gemm_proj<<<dim3(48, MM/128), 256, GEMM_SMEM>>>(xn, wt, proj);

    // 5-7: chunked associative scan (4-wide vectorized)
    scan_pass1<<<(BB*DD*CH)/(256*4), 256>>>(proj, Ar, Ai, Kr, Ki);
    scan_pass2<<<(BB*DD)/256, 256>>>(Ar, Ai, Kr, Ki, Hr, Hi);
    scan_pass3<<<(BB*DD*CH)/(256*4), 256>>>(proj, Hr, Hi, y);

    // 8: output projection
    gemm_f16<<<dim3(8, MM/128), 256, GEMM_SMEM>>>(
        y, wt + WO_OFF, out, 1024);
}

// round 17
// speedup vs baseline: 1.6576x; 1.0411x over previous
#include <cuda_runtime.h>
#include <cuda_fp16.h>
#include <math.h>
#include <stdint.h>

// ---------------- problem constants ----------------
#define BB 4
#define SS 4096
#define DD 1024
#define MM (BB*SS)            // 16384 rows
#define BSD (BB*SS*DD)
#define CH  64                // scan chunks
#define CL  (SS/CH)           // 64 steps per chunk
#define NCARR (CH*BB*DD)

// concatenated transposed-weight row offsets: [q|k|v|g|o|a]
#define WQ_OFF 0
#define WK_OFF (1024*DD)
#define WV_OFF (2048*DD)
#define WG_OFF (3072*DD)
#define WO_OFF (4096*DD)
#define WA_OFF (5120*DD)
#define WT_ROWS 7168
#define NPROJ 6144            // fused projection output width

// ---------------- device scratch (allocation-free) ----------------
__device__ __half g_xn[BSD];
__device__ __half g_y [BSD];
__device__ float g_proj[(size_t)MM*NPROJ];
__device__ __half g_wt[(size_t)WT_ROWS*DD];
__device__ float g_Ar[NCARR], g_Ai[NCARR], g_Kr[NCARR], g_Ki[NCARR];
__device__ float g_Hr[NCARR], g_Hi[NCARR];

// ---------------- ptx helpers ----------------
__device__ __forceinline__ uint32_t s2u(const void* p) {
    uint32_t a;
    asm("{ .reg .u64 t; cvta.to.shared.u64 t, %1; cvt.u32.u64 %0, t; }" : "=r"(a) : "l"(p));
    return a;
}
__device__ __forceinline__ void cp16(uint32_t s, const void* g) {
    asm volatile("cp.async.cg.shared.global [%0], [%1], 16;" :: "r"(s), "l"(g));
}
__device__ __forceinline__ void cp_commit() { asm volatile("cp.async.commit_group;" ::: "memory"); }
template<int N> __device__ __forceinline__ void cp_wait() {
    asm volatile("cp.async.wait_group %0;" :: "n"(N) : "memory");
}
__device__ __forceinline__ void ldsm4(uint32_t* r, uint32_t addr) {
    asm volatile("ldmatrix.sync.aligned.m8n8.x4.shared.b16 {%0,%1,%2,%3}, [%4];"
        : "=r"(r[0]), "=r"(r[1]), "=r"(r[2]), "=r"(r[3]) : "r"(addr));
}
__device__ __forceinline__ void mma16816(float* c, const uint32_t* a, uint32_t b0, uint32_t b1) {
    asm volatile(
        "mma.sync.aligned.m16n8k16.row.col.f32.f16.f16.f32 "
        "{%0,%1,%2,%3}, {%4,%5,%6,%7}, {%8,%9}, {%0,%1,%2,%3};"
        : "+f"(c[0]), "+f"(c[1]), "+f"(c[2]), "+f"(c[3])
        : "r"(a[0]), "r"(a[1]), "r"(a[2]), "r"(a[3]), "r"(b0), "r"(b1));
}
// SW128 swizzle of (row, byte-col within 128B row)
__device__ __forceinline__ uint32_t swz(uint32_t row, uint32_t kb) {
    uint32_t bo = row*128 + kb;
    return bo ^ ((bo >> 3) & 0x70);
}

// ---------------- fused weight prep: all 6 weights, one launch ----------------
__global__ __launch_bounds__(256) void wprep(
    const float* __restrict__ wq, const float* __restrict__ wk,
    const float* __restrict__ wv, const float* __restrict__ wg,
    const float* __restrict__ wo, const float* __restrict__ wa,
    __half* __restrict__ T)
{
    __shared__ float t[32][33];
    const int z = blockIdx.z;
    const float* W;
    size_t off;
    int N;
    switch (z) {
        case 0: W = wq; off = WQ_OFF; N = 1024; break;
        case 1: W = wk; off = WK_OFF; N = 1024; break;
        case 2: W = wv; off = WV_OFF; N = 1024; break;
        case 3: W = wg; off = WG_OFF; N = 1024; break;
        case 4: W = wo; off = WO_OFF; N = 1024; break;
        default: W = wa; off = WA_OFF; N = 2048; break;
    }
    const int n0 = blockIdx.x * 32;
    if (n0 >= N) return;
    const int k0 = blockIdx.y * 32;
    for (int i = threadIdx.y; i < 32; i += 8)
        t[i][threadIdx.x] = W[(size_t)(k0 + i) * N + n0 + threadIdx.x];
    __syncthreads();
    for (int i = threadIdx.y; i < 32; i += 8) {
        size_t o = off + (size_t)(n0 + i) * DD + k0 + threadIdx.x;
        T[o] = __float2half(t[threadIdx.x][i]);
    }
}

// ---------------- RMSNorm (fp16 output; row offset) ----------------
__global__ __launch_bounds__(256) void rmsnorm_h(
    const float* __restrict__ x, const float* __restrict__ scale,
    __half* __restrict__ o, int row0)
{
    const int row = row0 + blockIdx.x;
    const float* xr = x + (size_t)row * DD;
    float v[4];
    float s = 0.f;
#pragma unroll
    for (int i = 0; i < 4; i++) {
        v[i] = xr[threadIdx.x + i*256];
        s += v[i]*v[i];
    }
#pragma unroll
    for (int off = 16; off > 0; off >>= 1) s += __shfl_xor_sync(0xffffffffu, s, off);
    __shared__ float red[8];
    if ((threadIdx.x & 31) == 0) red[threadIdx.x >> 5] = s;
    __syncthreads();
    float tot = red[0]+red[1]+red[2]+red[3]+red[4]+red[5]+red[6]+red[7];
    float inv = rsqrtf(tot * (1.f/DD) + 1e-6f);
    size_t base = (size_t)row * DD;
#pragma unroll
    for (int i = 0; i < 4; i++) {
        int idx = threadIdx.x + i*256;
        o[base + idx] = __float2half(v[i] * inv * scale[idx]);
    }
}

// ---------------- HMMA fp16 GEMM core (single term, K-chunk = 128) ----------------
#define NSTG 3
#define NCH  8             // 1024 / 128
// stage layout: A sub0 | A sub1 | B sub0 | B sub1  (each 16KB = 128 rows x 128B)
#define OFF_A0 0
#define OFF_A1 16384
#define OFF_B0 32768
#define OFF_B1 49152
#define STAGE_BYTES 65536
#define GEMM_SMEM (NSTG*STAGE_BYTES)   // 192KB

__device__ __forceinline__ void load_stage(
    uint32_t st, const __half* A, const __half* B, int kc, int tid)
{
    const int gcol = tid & 7, r0 = tid >> 3;        // 256 threads: r0 in [0,32)
#pragma unroll
    for (int sub = 0; sub < 2; sub++) {
        const int ko = kc*128 + sub*64 + gcol*8;
        const uint32_t so = (uint32_t)sub * 16384;
#pragma unroll
        for (int rr = 0; rr < 128; rr += 32) {
            int r = r0 + rr;
            uint32_t bo = r*128 + gcol*16;
            uint32_t sw = bo ^ ((bo >> 3) & 0x70);
            size_t go = (size_t)r * DD + ko;
            cp16(st + OFF_A0 + so + sw, A + go);
            cp16(st + OFF_B0 + so + sw, B + go);
        }
    }
}

// mainloop: 8 warps, warp tile 32(M) x 64(N); acc[2][8][4] = 64 regs
__device__ __forceinline__ void gemm_mainloop(
    uint32_t sb, int tid, const __half* pA, const __half* pB,
    int aRow, int bRow, uint32_t kbl, float acc[2][8][4])
{
#pragma unroll
    for (int c = 0; c < NSTG-1; c++) {
        load_stage(sb + c*STAGE_BYTES, pA, pB, c, tid);
        cp_commit();
    }

    for (int c = 0; c < NCH; c++) {
        if (c < NCH - (NSTG-1)) cp_wait<NSTG-2>(); else cp_wait<0>();
        __syncthreads();
        if (c + NSTG-1 < NCH) {
            load_stage(sb + ((c + NSTG-1) % NSTG)*STAGE_BYTES, pA, pB, c + NSTG-1, tid);
            cp_commit();
        }
        const uint32_t stg = sb + (c % NSTG)*STAGE_BYTES;
#pragma unroll
        for (int ks = 0; ks < 8; ks++) {
            const uint32_t sub = (uint32_t)(ks >> 2) * 16384;
            const uint32_t kb = (ks & 3)*32 + kbl;
            uint32_t af[2][4], bf[4][4];
            ldsm4(af[0], stg + OFF_A0 + sub + swz(aRow,      kb));
            ldsm4(af[1], stg + OFF_A0 + sub + swz(aRow + 16, kb));
#pragma unroll
            for (int nn = 0; nn < 4; nn++)
                ldsm4(bf[nn], stg + OFF_B0 + sub + swz(bRow + nn*16, kb));
            // 16 MMAs, each accumulator written once -> RAW distance 16
#pragma unroll
            for (int mt = 0; mt < 2; mt++)
#pragma unroll
                for (int nn = 0; nn < 4; nn++) {
                    mma16816(acc[mt][nn*2],   af[mt], bf[nn][0], bf[nn][2]);
                    mma16816(acc[mt][nn*2+1], af[mt], bf[nn][1], bf[nn][3]);
                }
        }
    }
}

// generic GEMM: C[M, ldc] tile at (m0, n0)
__global__ void __launch_bounds__(256, 1) gemm_f16(
    const __half* __restrict__ A, const __half* __restrict__ B,
    float* __restrict__ C, int ldc)
{
    extern __shared__ char smem[];
    const uint32_t sb = s2u(smem);
    const int tid = threadIdx.x, wid = tid >> 5, lane = tid & 31;
    const int wm = wid & 3, wn = wid >> 2;          // warp grid 4(M) x 2(N)
    const int m0 = blockIdx.y << 7, n0 = blockIdx.x << 7;

    float acc[2][8][4];
#pragma unroll
    for (int i = 0; i < 2; i++)
#pragma unroll
        for (int j = 0; j < 8; j++)
#pragma unroll
            for (int t = 0; t < 4; t++) acc[i][j][t] = 0.f;

    const int aRow = wm*32 + (lane & 15);
    const int bRow = wn*64 + (lane & 15);
    const uint32_t kbl = (uint32_t)(lane >> 4) * 16;

    gemm_mainloop(sb, tid, A + (size_t)m0 * DD, B + (size_t)n0 * DD,
                  aRow, bRow, kbl, acc);

    const int erow = lane >> 2;
    const int ecol = (lane & 3) * 2;
#pragma unroll
    for (int mt = 0; mt < 2; mt++) {
#pragma unroll
        for (int nt = 0; nt < 8; nt++) {
            int row = m0 + wm*32 + mt*16 + erow;
            int col = n0 + wn*64 + nt*8 + ecol;
            float2* p0 = (float2*)(C + (size_t)row * ldc + col);
            float2* p1 = (float2*)(C + (size_t)(row + 8) * ldc + col);
            *p0 = make_float2(acc[mt][nt][0], acc[mt][nt][1]);
            *p1 = make_float2(acc[mt][nt][2], acc[mt][nt][3]);
        }
    }
}

// proj GEMM: bx<32 -> cols [0,4096) from wt rows [0,4096); bx>=32 -> cols [4096,6144) from wt rows [WA_OFF,...)
__global__ void __launch_bounds__(256, 1) gemm_proj(
    const __half* __restrict__ A, const __half* __restrict__ wt,
    float* __restrict__ C)
{
    extern __shared__ char smem[];
    const uint32_t sb = s2u(smem);
    const int tid = threadIdx.x, wid = tid >> 5, lane = tid & 31;
    const int wm = wid & 3, wn = wid >> 2;
    const int m0 = blockIdx.y << 7;
    int bx = blockIdx.x;
    const __half* B;
    int n0c;
    if (bx < 32) { B = wt + (size_t)(bx << 7) * DD;                       n0c = bx << 7; }
    else         { B = wt + (size_t)WA_OFF + (size_t)((bx-32) << 7) * DD; n0c = 4096 + ((bx-32) << 7); }

    float acc[2][8][4];
#pragma unroll
    for (int i = 0; i < 2; i++)
#pragma unroll
        for (int j = 0; j < 8; j++)
#pragma unroll
            for (int t = 0; t < 4; t++) acc[i][j][t] = 0.f;

    const int aRow = wm*32 + (lane & 15);
    const int bRow = wn*64 + (lane & 15);
    const uint32_t kbl = (uint32_t)(lane >> 4) * 16;

    gemm_mainloop(sb, tid, A + (size_t)m0 * DD, B, aRow, bRow, kbl, acc);

    const int erow = lane >> 2;
    const int ecol = (lane & 3) * 2;
#pragma unroll
    for (int mt = 0; mt < 2; mt++) {
#pragma unroll
        for (int nt = 0; nt < 8; nt++) {
            int row = m0 + wm*32 + mt*16 + erow;
            int col = n0c + wn*64 + nt*8 + ecol;
            float2* p0 = (float2*)(C + (size_t)row * NPROJ + col);
            float2* p1 = (float2*)(C + (size_t)(row + 8) * NPROJ + col);
            *p0 = make_float2(acc[mt][nt][0], acc[mt][nt][1]);
            *p1 = make_float2(acc[mt][nt][2], acc[mt][nt][3]);
        }
    }
}

// ---------------- gate helper ----------------
__device__ __forceinline__ void gate_a(float ar, float ai, float& car, float& cai)
{
    float r = sqrtf(ar*ar + ai*ai);
    float sig = 1.f / (1.f + __expf(-r));
    if (r > 1e-30f) {
        float sc = sig / r;
        car = ar * sc;
        cai = ai * sc;
    } else {
        car = 0.5f;
        cai = 0.f;
    }
}

// proj layout: row-major [MM, 6144]: q|k|v|g|ar|ai
#define PQ 0
#define PK 1024
#define PV 2048
#define PG 3072
#define PAR 4096
#define PAI 5120

// ---------------- scan pass 1 (4 lanes/thread, float4 loads) ----------------
__global__ __launch_bounds__(256) void scan_pass1(
    const float* __restrict__ proj,
    float* __restrict__ Ar, float* __restrict__ Ai,
    float* __restrict__ Kr, float* __restrict__ Ki)
{
    const int idx = blockIdx.x * 256 + threadIdx.x;   // [0, 65536)
    const int d4 = (idx & 255) << 2;
    const int bc = idx >> 8;
    const int b  = bc & (BB-1);
    const int c  = bc >> 2;
    float Are[4], Aim[4], Kre[4], Kim[4];
#pragma unroll
    for (int j = 0; j < 4; j++) { Are[j] = 1.f; Aim[j] = 0.f; Kre[j] = 0.f; Kim[j] = 0.f; }
    const size_t rowbase = (size_t)b * SS + (size_t)c * CL;
    for (int t = 0; t < CL; t++) {
        const float* pr = proj + (rowbase + t) * NPROJ;
        float4 var = *(const float4*)(pr + PAR + d4);
        float4 vai = *(const float4*)(pr + PAI + d4);
        float4 vk  = *(const float4*)(pr + PK  + d4);
        float4 vv  = *(const float4*)(pr + PV  + d4);
        float arr[4] = {var.x, var.y, var.z, var.w};
        float aii[4] = {vai.x, vai.y, vai.z, vai.w};
        float kk [4] = {vk.x,  vk.y,  vk.z,  vk.w};
        float vvv[4] = {vv.x,  vv.y,  vv.z,  vv.w};
#pragma unroll
        for (int j = 0; j < 4; j++) {
            float car, cai;
            gate_a(arr[j], aii[j], car, cai);
            float kv = kk[j] * vvv[j];
            float nAr = car*Are[j] - cai*Aim[j];
            float nAi = car*Aim[j] + cai*Are[j];
            float nKr = car*Kre[j] - cai*Kim[j] + kv;
            float nKi = car*Kim[j] + cai*Kre[j];
            Are[j] = nAr; Aim[j] = nAi; Kre[j] = nKr; Kim[j] = nKi;
        }
    }
    const int cb = ((c << 2) + b) * DD + d4;
    *(float4*)(Ar + cb) = make_float4(Are[0], Are[1], Are[2], Are[3]);
    *(float4*)(Ai + cb) = make_float4(Aim[0], Aim[1], Aim[2], Aim[3]);
    *(float4*)(Kr + cb) = make_float4(Kre[0], Kre[1], Kre[2], Kre[3]);
    *(float4*)(Ki + cb) = make_float4(Kim[0], Kim[1], Kim[2], Kim[3]);
}

// ---------------- scan pass 2 ----------------
__global__ __launch_bounds__(256) void scan_pass2(
    const float* __restrict__ Ar, const float* __restrict__ Ai,
    const float* __restrict__ Kr, const float* __restrict__ Ki,
    float* __restrict__ Hr, float* __restrict__ Hi)
{
    const int idx = blockIdx.x * 256 + threadIdx.x;  // B*D
    const int d = idx & (DD-1);
    const int b = idx >> 10;
    float hr = 0.f, hi = 0.f;
    for (int c = 0; c < CH; c++) {
        const int cidx = ((c << 2) + b) * DD + d;
        Hr[cidx] = hr; Hi[cidx] = hi;
        float ar = Ar[cidx], ai = Ai[cidx];
        float kr = Kr[cidx], ki = Ki[cidx];
        float nhr = ar*hr - ai*hi + kr;
        float nhi = ar*hi + ai*hr + ki;
        hr = nhr; hi = nhi;
    }
}

// ---------------- scan pass 3 (4 lanes/thread; emits y fp16) ----------------
__global__ __launch_bounds__(256) void scan_pass3(
    const float* __restrict__ proj,
    const float* __restrict__ Hr, const float* __restrict__ Hi,
    __half* __restrict__ y)
{
    const int idx = blockIdx.x * 256 + threadIdx.x;
    const int d4 = (idx & 255) << 2;
    const int bc = idx >> 8;
    const int b  = bc & (BB-1);
    const int c  = bc >> 2;
    const int cb = ((c << 2) + b) * DD + d4;
    float4 h0 = *(const float4*)(Hr + cb);
    float4 h1 = *(const float4*)(Hi + cb);
    float hr[4] = {h0.x, h0.y, h0.z, h0.w};
    float hi[4] = {h1.x, h1.y, h1.z, h1.w};
    const size_t rowbase = (size_t)b * SS + (size_t)c * CL;
    for (int t = 0; t < CL; t++) {
        const size_t row = rowbase + t;
        const float* pr = proj + row * NPROJ;
        float4 var = *(const float4*)(pr + PAR + d4);
        float4 vai = *(const float4*)(pr + PAI + d4);
        float4 vk  = *(const float4*)(pr + PK  + d4);
        float4 vv  = *(const float4*)(pr + PV  + d4);
        float4 vq  = *(const float4*)(pr + PQ  + d4);
        float4 vg  = *(const float4*)(pr + PG  + d4);
        float arr[4] = {var.x, var.y, var.z, var.w};
        float aii[4] = {vai.x, vai.y, vai.z, vai.w};
        float kk [4] = {vk.x,  vk.y,  vk.z,  vk.w};
        float vvv[4] = {vv.x,  vv.y,  vv.z,  vv.w};
        float qq [4] = {vq.x,  vq.y,  vq.z,  vq.w};
        float gg [4] = {vg.x,  vg.y,  vg.z,  vg.w};
        __half oh[4];
#pragma unroll
        for (int j = 0; j < 4; j++) {
            float car, cai;
            gate_a(arr[j], aii[j], car, cai);
            float kv = kk[j] * vvv[j];
            float nhr = car*hr[j] - cai*hi[j] + kv;
            float nhi = car*hi[j] + cai*hr[j];
            hr[j] = nhr; hi[j] = nhi;
            float silu = gg[j] / (1.f + __expf(-gg[j]));
            oh[j] = __float2half(qq[j] * hr[j] * silu);
        }
        const size_t off = row * DD + d4;
        *(__half2*)(y + off)     = __halves2half2(oh[0], oh[1]);
        *(__half2*)(y + off + 2) = __halves2half2(oh[2], oh[3]);
    }
}

// ---------------- launch ----------------
extern "C" void kernel_launch(void* const* d_in, const int* in_sizes, int n_in,
                              void* d_out, int out_size)
{
    const float* x    = (const float*)d_in[0];
    const float* wq   = (const float*)d_in[1];
    const float* wk   = (const float*)d_in[2];
    const float* wv   = (const float*)d_in[3];
    const float* wa   = (const float*)d_in[4];
    const float* wg   = (const float*)d_in[5];
    const float* wo   = (const float*)d_in[6];
    const float* rmsw = (const float*)d_in[7];
    float* out = (float*)d_out;

    __half *xn, *y, *wt;
    float *proj;
    float *Ar, *Ai, *Kr, *Ki, *Hr, *Hi;
    cudaGetSymbolAddress((void**)&xn, g_xn);
    cudaGetSymbolAddress((void**)&y,  g_y);
    cudaGetSymbolAddress((void**)&wt, g_wt);
    cudaGetSymbolAddress((void**)&proj, g_proj);
    cudaGetSymbolAddress((void**)&Ar, g_Ar);
    cudaGetSymbolAddress((void**)&Ai, g_Ai);
    cudaGetSymbolAddress((void**)&Kr, g_Kr);
    cudaGetSymbolAddress((void**)&Ki, g_Ki);
    cudaGetSymbolAddress((void**)&Hr, g_Hr);
    cudaGetSymbolAddress((void**)&Hi, g_Hi);

    cudaFuncSetAttribute(gemm_f16, cudaFuncAttributeMaxDynamicSharedMemorySize, GEMM_SMEM);
    cudaFuncSetAttribute(gemm_proj, cudaFuncAttributeMaxDynamicSharedMemorySize, GEMM_SMEM);

    // 1: fused weight prep (all 6 weights)
    wprep<<<dim3(64, 32, 6), dim3(32, 8)>>>(wq, wk, wv, wg, wo, wa, wt);

    // 2-3: RMSNorm in two halves (keeps GEMM at launch #4 for ncu capture)
    rmsnorm_h<<<MM/2, 256>>>(x, rmsw, xn, 0);
    rmsnorm_h<<<MM/2, 256>>>(x, rmsw, xn, MM/2);

    // 4: fused q|k|v|g|a projection GEMM  [16384 x 6144]
    gemm_proj<<<dim3(48, MM/128), 256, GEMM_SMEM>>>(xn, wt, proj);

    // 5-7: chunked associative scan (4-wide vectorized)
    scan_pass1<<<(BB*DD*CH)/(256*4), 256>>>(proj, Ar, Ai, Kr, Ki);
    scan_pass2<<<(BB*DD)/256, 256>>>(Ar, Ai, Kr, Ki, Hr, Hi);
    scan_pass3<<<(BB*DD*CH)/(256*4), 256>>>(proj, Hr, Hi, y);

    // 8: output projection
    gemm_f16<<<dim3(8, MM/128), 256, GEMM_SMEM>>>(
        y, wt + WO_OFF, out, 1024);
}